// round 9
// baseline (speedup 1.0000x reference)
#include <cuda_runtime.h>
#include <cstdint>

#define BATCH    64
#define SEQ      8192
#define RDIM     80
#define RING     169          // write slot disjoint from all read slots mod 169
#define NTHREADS 416          // warps 0-2: consumers (96 thr), warps 3-12: producers (320 thr)
#define NCONS    96
#define PART_DEPTH 8          // partial ring depth (producer lead <= 4)

typedef unsigned long long u64;

__device__ __forceinline__ u64 ffma2(u64 a, u64 b, u64 c) {
    u64 d;
    asm("fma.rn.f32x2 %0, %1, %2, %3;" : "=l"(d) : "l"(a), "l"(b), "l"(c));
    return d;
}

__device__ __forceinline__ float2 unpack2(u64 v) {
    unsigned lo, hi;
    asm("mov.b64 {%0, %1}, %2;" : "=r"(lo), "=r"(hi) : "l"(v));
    float2 r;
    r.x = __uint_as_float(lo);
    r.y = __uint_as_float(hi);
    return r;
}

__device__ __forceinline__ float fast_tanh(float v) {
    v = fminf(fmaxf(v, -15.0f), 15.0f);
    float u = __expf(-2.0f * v);
    return __fdividef(1.0f - u, 1.0f + u);
}

// Barrier plan (all counts = NTHREADS except consumer-internal):
//   ids 2..5 : P ring  (partials gen g uses id 2 + (g&3)); producers arrive, consumers sync
//   ids 6..9 : H ring  (h gen g uses id 6 + (g&3));        consumers arrive, producers sync
//   id  10   : consumer-internal sync (96 threads)
#define BAR_SYNC(id)   asm volatile("bar.sync %0, %1;"   :: "r"(id), "n"(NTHREADS) : "memory")
#define BAR_ARRIVE(id) asm volatile("bar.arrive %0, %1;" :: "r"(id), "n"(NTHREADS) : "memory")
#define BAR_SYNC_C()   asm volatile("bar.sync 10, %0;"   :: "n"(NCONS) : "memory")

__global__ __launch_bounds__(NTHREADS, 1)
void reservoir_kernel(const float* __restrict__ x,
                      const float* __restrict__ Win,
                      const float* __restrict__ Wfb,
                      const float* __restrict__ bias,
                      float* __restrict__ out)
{
    extern __shared__ float sm[];
    float* Hring = sm;                       // [RING][RDIM]          = 13520 f
    float* xs    = Hring + RING * RDIM;      // [SEQ]                 = 8192 f
    float* part  = xs + SEQ;                 // [PART_DEPTH][320]     = 2560 f

    const int b   = blockIdx.x;
    const int tid = threadIdx.x;

    for (int idx = tid; idx < RING * RDIM; idx += NTHREADS) Hring[idx] = 0.0f;
    const float* xb = x + (size_t)b * SEQ;
    for (int idx = tid; idx < SEQ; idx += NTHREADS) xs[idx] = xb[idx];

    float* outb = out + (size_t)b * SEQ * RDIM;

    __syncthreads();

    if (tid < NCONS) {
        // ================= CONSUMER: tau=1 + epilogue =================
        const int i = tid;                    // neuron (valid if < 80)
        u64 W1[40];
        float win_i = 0.0f, bias_i = 0.0f;
        if (tid < RDIM) {
            const float* wrow = Wfb + (size_t)i * RDIM;   // tap tau=1
#pragma unroll
            for (int p = 0; p < 40; p++) {
                unsigned lo = __float_as_uint(wrow[2 * p]);
                unsigned hi = __float_as_uint(wrow[2 * p + 1]);
                W1[p] = ((u64)hi << 32) | (u64)lo;
            }
            win_i  = Win[i];
            bias_i = bias[i];
        }
        float h_i = 0.0f;
        int w = 0, rm1 = RING - 1;

        // Priming: publish "h[-4..-1] = 0" (one arrival per H-ring instance)
        BAR_ARRIVE(6); BAR_ARRIVE(7); BAR_ARRIVE(8); BAR_ARRIVE(9);

#pragma unroll 1
        for (int t = 0; t < SEQ; ++t) {
            float fh = 0.0f;
            if (tid < RDIM) {
                // tau=1 full row vs h[t-1] (broadcast reads; own-group data)
                const ulonglong2* hv =
                    reinterpret_cast<const ulonglong2*>(Hring + rm1 * RDIM);
                u64 a0 = 0ull, a1 = 0ull, a2 = 0ull, a3 = 0ull;
#pragma unroll
                for (int p = 0; p < 10; p++) {
                    ulonglong2 A = hv[2 * p];
                    ulonglong2 B = hv[2 * p + 1];
                    a0 = ffma2(A.x, W1[4 * p + 0], a0);
                    a1 = ffma2(A.y, W1[4 * p + 1], a1);
                    a2 = ffma2(B.x, W1[4 * p + 2], a2);
                    a3 = ffma2(B.y, W1[4 * p + 3], a3);
                }
                float2 f0 = unpack2(a0);
                float2 f1 = unpack2(a1);
                float2 f2 = unpack2(a2);
                float2 f3 = unpack2(a3);
                fh = ((f0.x + f0.y) + (f1.x + f1.y)) +
                     ((f2.x + f2.y) + (f3.x + f3.y));
            }

            BAR_SYNC(2 + (t & 3));       // old-tap partials(t) ready

            if (tid < RDIM) {
                float4 p4 = *reinterpret_cast<const float4*>(
                    part + (t & (PART_DEPTH - 1)) * 320 + 4 * i);
                float f = fh + ((p4.x + p4.y) + (p4.z + p4.w));
                float val = fmaf(xs[t], win_i, f + bias_i);
                h_i = 0.7f * h_i + 0.3f * fast_tanh(val);
                Hring[w * RDIM + i] = h_i;          // slot t
                outb[(size_t)t * RDIM + i] = h_i;
            }

            BAR_ARRIVE(6 + (t & 3));     // publish h[t] (gen t+4 on H ring)
            BAR_SYNC_C();                // h[t] visible within consumer group

            ++w;   if (w   == RING) w   = 0;
            ++rm1; if (rm1 == RING) rm1 = 0;
        }
    } else {
        // ================= PRODUCER: old taps {4,24,96,168} =================
        const int q = tid - NCONS;        // 0..319
        const int k = q / RDIM;           // tap index 0..3
        const int i = q % RDIM;           // neuron
        const int tau = (k == 0) ? 4 : (k == 1) ? 24 : (k == 2) ? 96 : 168;

        u64 Wp[40];
        {
            const float* wrow = Wfb + ((size_t)(k + 1) * RDIM + i) * RDIM;
#pragma unroll
            for (int p = 0; p < 40; p++) {
                unsigned lo = __float_as_uint(wrow[2 * p]);
                unsigned hi = __float_as_uint(wrow[2 * p + 1]);
                Wp[p] = ((u64)hi << 32) | (u64)lo;
            }
        }

        int rk = RING - tau;              // slot of h[s - tau] at s=0

#pragma unroll 1
        for (int s = 0; s < SEQ; ++s) {
            BAR_SYNC(6 + (s & 3));        // h[s-4] published (gens 0-3 primed)

            const ulonglong2* hv =
                reinterpret_cast<const ulonglong2*>(Hring + rk * RDIM);
            u64 a0 = 0ull, a1 = 0ull, a2 = 0ull, a3 = 0ull;
#pragma unroll
            for (int p = 0; p < 10; p++) {
                ulonglong2 A = hv[2 * p];
                ulonglong2 B = hv[2 * p + 1];
                a0 = ffma2(A.x, Wp[4 * p + 0], a0);
                a1 = ffma2(A.y, Wp[4 * p + 1], a1);
                a2 = ffma2(B.x, Wp[4 * p + 2], a2);
                a3 = ffma2(B.y, Wp[4 * p + 3], a3);
            }
            float2 f0 = unpack2(a0);
            float2 f1 = unpack2(a1);
            float2 f2 = unpack2(a2);
            float2 f3 = unpack2(a3);
            part[(s & (PART_DEPTH - 1)) * 320 + 4 * i + k] =
                ((f0.x + f0.y) + (f1.x + f1.y)) + ((f2.x + f2.y) + (f3.x + f3.y));

            BAR_ARRIVE(2 + (s & 3));      // publish partials(s)

            ++rk; if (rk == RING) rk = 0;
        }
    }
}

extern "C" void kernel_launch(void* const* d_in, const int* in_sizes, int n_in,
                              void* d_out, int out_size)
{
    const float* x    = (const float*)d_in[0];  // [64, 8192, 1]
    const float* Win  = (const float*)d_in[1];  // [80, 1]
    const float* Wfb  = (const float*)d_in[2];  // [5, 80, 80]
    const float* bias = (const float*)d_in[3];  // [80]
    float* out = (float*)d_out;                 // [64, 8192, 80]

    const int smem_bytes =
        (RING * RDIM + SEQ + PART_DEPTH * 320) * sizeof(float);
    cudaFuncSetAttribute(reservoir_kernel,
                         cudaFuncAttributeMaxDynamicSharedMemorySize, smem_bytes);

    reservoir_kernel<<<BATCH, NTHREADS, smem_bytes>>>(x, Win, Wfb, bias, out);
}

// round 10
// speedup vs baseline: 1.2741x; 1.2741x over previous
#include <cuda_runtime.h>
#include <cstdint>

#define BATCH    64
#define SEQ      8192
#define RDIM     80
#define NTAPS    5
#define RING     169          // write slot disjoint from all read slots mod 169
#define NTHREADS 320          // i = tid % 80, jh = tid / 80
#define JSLICE   20
#define NPAIR    10
#define FLUSH    64           // output flush chunk (rows)

typedef unsigned long long u64;

__device__ __forceinline__ u64 ffma2(u64 a, u64 b, u64 c) {
    u64 d;
    asm("fma.rn.f32x2 %0, %1, %2, %3;" : "=l"(d) : "l"(a), "l"(b), "l"(c));
    return d;
}

__device__ __forceinline__ float2 unpack2(u64 v) {
    unsigned lo, hi;
    asm("mov.b64 {%0, %1}, %2;" : "=r"(lo), "=r"(hi) : "l"(v));
    float2 r;
    r.x = __uint_as_float(lo);
    r.y = __uint_as_float(hi);
    return r;
}

__device__ __forceinline__ float fast_tanh(float v) {
    v = fminf(fmaxf(v, -15.0f), 15.0f);
    float u = __expf(-2.0f * v);
    return __fdividef(1.0f - u, 1.0f + u);
}

// Accumulate one tap row (20 floats at hrow) against Wp[k][*]
#define TAP_ACC(k, hrow)                                                  \
    do {                                                                  \
        const ulonglong2* hv = reinterpret_cast<const ulonglong2*>(hrow); \
        ulonglong2 h01 = hv[0];                                           \
        ulonglong2 h23 = hv[1];                                           \
        ulonglong2 h45 = hv[2];                                           \
        ulonglong2 h67 = hv[3];                                           \
        ulonglong2 h89 = hv[4];                                           \
        a0 = ffma2(h01.x, Wp[k][0], a0);                                  \
        a1 = ffma2(h01.y, Wp[k][1], a1);                                  \
        a2 = ffma2(h23.x, Wp[k][2], a2);                                  \
        a3 = ffma2(h23.y, Wp[k][3], a3);                                  \
        a0 = ffma2(h45.x, Wp[k][4], a0);                                  \
        a1 = ffma2(h45.y, Wp[k][5], a1);                                  \
        a2 = ffma2(h67.x, Wp[k][6], a2);                                  \
        a3 = ffma2(h67.y, Wp[k][7], a3);                                  \
        a0 = ffma2(h89.x, Wp[k][8], a0);                                  \
        a1 = ffma2(h89.y, Wp[k][9], a1);                                  \
    } while (0)

__global__ __launch_bounds__(NTHREADS, 1)
void reservoir_kernel(const float* __restrict__ x,
                      const float* __restrict__ Win,
                      const float* __restrict__ Wfb,
                      const float* __restrict__ bias,
                      float* __restrict__ out)
{
    extern __shared__ float sm[];
    float* Hring = sm;                     // [RING][RDIM] = 13520 f
    float* xs    = Hring + RING * RDIM;    // [SEQ]        = 8192 f
    float* part  = xs + SEQ;               // [NTHREADS]   = 320 f (part[i*4+jh])

    const int b   = blockIdx.x;
    const int tid = threadIdx.x;
    const int i   = tid % RDIM;   // neuron index
    const int jh  = tid / RDIM;   // j-quarter 0..3

    for (int idx = tid; idx < RING * RDIM; idx += NTHREADS) Hring[idx] = 0.0f;

    const float* xb = x + (size_t)b * SEQ;
    for (int idx = tid; idx < SEQ; idx += NTHREADS) xs[idx] = xb[idx];

    // feedback[i] = sum_k sum_j delayed[k][j] * Wfb[k][i][j]
    u64 Wp[NTAPS][NPAIR];
#pragma unroll
    for (int k = 0; k < NTAPS; k++) {
        const float* wrow = Wfb + ((size_t)k * RDIM + i) * RDIM + jh * JSLICE;
#pragma unroll
        for (int p = 0; p < NPAIR; p++) {
            unsigned lo = __float_as_uint(wrow[2 * p]);
            unsigned hi = __float_as_uint(wrow[2 * p + 1]);
            Wp[k][p] = ((u64)hi << 32) | (u64)lo;
        }
    }

    float win_i = 0.0f, bias_i = 0.0f, h_i = 0.0f;
    if (tid < RDIM) { win_i = Win[tid]; bias_i = bias[tid]; }

    float* outb = out + (size_t)b * SEQ * RDIM;
    const float* hbase = Hring + jh * JSLICE;

    // Ring slots at t=0: write w=0; reads r_k = (0 - tau_k) mod 169
    int w  = 0;
    int r0 = RING - 1;    // tau 1
    int r1 = RING - 4;    // tau 4
    int r2 = RING - 24;   // tau 24
    int r3 = RING - 96;   // tau 96
    int r4 = RING - 168;  // tau 168

    __syncthreads();

#pragma unroll 1
    for (int t = 0; t < SEQ; ++t) {
        u64 a0 = 0ull, a1 = 0ull, a2 = 0ull, a3 = 0ull;

        // ---- P1: old taps {4,24,96,168} (need h[t-4] and older; visible
        // since BAR A of step t-3). Overlaps epilogue of step t-1.
        TAP_ACC(1, hbase + r1 * RDIM);
        TAP_ACC(2, hbase + r2 * RDIM);
        TAP_ACC(3, hbase + r3 * RDIM);
        TAP_ACC(4, hbase + r4 * RDIM);

        // ---- Lazy output flush: once per 64 steps, copy rows [t-65, t-1)
        // from the smem ring to GMEM. All rows <= t-2: visible since
        // BAR A(t-1); disjoint from epilogue(t-1)'s write slot (t-1)%169.
        // STG drain cost is paid once per 64 steps at BAR A instead of
        // every step in the epilogue.
        if ((t & (FLUSH - 1)) == 1 && t >= FLUSH + 1) {
            int wbase = w + (RING - FLUSH - 1);        // slot of row t-65
            if (wbase >= RING) wbase -= RING;
#pragma unroll
            for (int k = 0; k < 4; ++k) {
                int f = k * NTHREADS + tid;            // float4 id 0..1279
                int row_off = f / 20;
                int col4 = f % 20;
                int s = wbase + row_off;
                if (s >= RING) s -= RING;
                float4 v = *reinterpret_cast<const float4*>(
                    Hring + s * RDIM + col4 * 4);
                *reinterpret_cast<float4*>(
                    outb + (size_t)(t - FLUSH - 1 + row_off) * RDIM + col4 * 4) = v;
            }
        }

        const float x_t = xs[t];

        // ---- BAR A: h[t-1] (epilogue of t-1) visible.
        __syncthreads();

        // ---- P2: tau=1 (needs h[t-1]) + partial store
        TAP_ACC(0, hbase + r0 * RDIM);

        float2 f0 = unpack2(a0);
        float2 f1 = unpack2(a1);
        float2 f2 = unpack2(a2);
        float2 f3 = unpack2(a3);
        part[i * 4 + jh] =
            ((f0.x + f0.y) + (f1.x + f1.y)) + ((f2.x + f2.y) + (f3.x + f3.y));

        // ---- BAR B: partials visible.
        __syncthreads();

        // ---- Epilogue (80 threads): reduce + tanh + smem-only publish.
        if (tid < RDIM) {
            float4 p4 = *reinterpret_cast<const float4*>(part + 4 * tid);
            float f = (p4.x + p4.y) + (p4.z + p4.w);
            float val = fmaf(x_t, win_i, f + bias_i);
            h_i = 0.7f * h_i + 0.3f * fast_tanh(val);
            Hring[w * RDIM + tid] = h_i;               // slot t (smem only!)
        }

        ++w;  if (w  == RING) w  = 0;
        ++r0; if (r0 == RING) r0 = 0;
        ++r1; if (r1 == RING) r1 = 0;
        ++r2; if (r2 == RING) r2 = 0;
        ++r3; if (r3 == RING) r3 = 0;
        ++r4; if (r4 == RING) r4 = 0;
    }

    // ---- Tail flush: last 64 rows [SEQ-64, SEQ)
    __syncthreads();
    {
        int wbase = w - FLUSH;                // w = SEQ % 169 here
        if (wbase < 0) wbase += RING;
#pragma unroll
        for (int k = 0; k < 4; ++k) {
            int f = k * NTHREADS + tid;
            int row_off = f / 20;
            int col4 = f % 20;
            int s = wbase + row_off;
            if (s >= RING) s -= RING;
            float4 v = *reinterpret_cast<const float4*>(
                Hring + s * RDIM + col4 * 4);
            *reinterpret_cast<float4*>(
                outb + (size_t)(SEQ - FLUSH + row_off) * RDIM + col4 * 4) = v;
        }
    }
}

extern "C" void kernel_launch(void* const* d_in, const int* in_sizes, int n_in,
                              void* d_out, int out_size)
{
    const float* x    = (const float*)d_in[0];  // [64, 8192, 1]
    const float* Win  = (const float*)d_in[1];  // [80, 1]
    const float* Wfb  = (const float*)d_in[2];  // [5, 80, 80]
    const float* bias = (const float*)d_in[3];  // [80]
    float* out = (float*)d_out;                 // [64, 8192, 80]

    const int smem_bytes = (RING * RDIM + SEQ + NTHREADS) * sizeof(float);
    cudaFuncSetAttribute(reservoir_kernel,
                         cudaFuncAttributeMaxDynamicSharedMemorySize, smem_bytes);

    reservoir_kernel<<<BATCH, NTHREADS, smem_bytes>>>(x, Win, Wfb, bias, out);
}